// round 15
// baseline (speedup 1.0000x reference)
#include <cuda_runtime.h>
#include <cuda_bf16.h>
#include <math.h>

// ---------------- problem constants ----------------
constexpr int B_   = 4096;
constexpr int U_   = 6;
constexpr int I_   = 1024;
constexpr int H_   = 512;
constexpr int IK_  = 64;
constexpr int IV_  = 400;
constexpr int IVP  = 416;                     // IV padded to mult of 16
constexpr int KTOP = 4;
constexpr int CH_  = 4;
constexpr int CK_  = 32;
constexpr int CV_  = 512;
constexpr int NS_  = 4;
constexpr int H3_  = 3 * H_;                  // 1536
constexpr int CHCV = CH_ * CV_;               // 2048
constexpr int QKVN = CH_*CK_ + CH_*CK_ + CHCV; // 2304
constexpr int UH_  = U_ * H_;                 // 3072
constexpr int UCV  = U_ * CHCV;               // 12288

// ---------------- fp32 scratch ----------------
__device__ __align__(256) float g_k0[B_ * IK_];
__device__ __align__(256) float g_ql[B_ * U_ * IK_];
__device__ __align__(256) float g_p0[B_ * U_];
__device__ __align__(256) float g_p1[B_ * U_];
__device__ __align__(256) float g_mask[B_ * U_];
__device__ __align__(256) float g_Wx[U_ * IV_ * H3_];     // fp32 kept for bvwx
__device__ __align__(256) float g_bvWx[U_ * H3_];
__device__ __align__(256) float g_gx[B_ * U_ * H3_];
__device__ __align__(256) float g_gh[B_ * U_ * H3_];
__device__ __align__(256) float g_hb[B_ * U_ * H_];
__device__ __align__(256) float g_qkv[B_ * U_ * QKVN];

// ---------------- bf16 hi/lo scratch (zero-init covers K padding) --------
__device__ __align__(256) __nv_bfloat16 g_v0h[B_ * IVP], g_v0l[B_ * IVP];
__device__ __align__(256) __nv_bfloat16 g_hsh[B_ * UH_], g_hsl[B_ * UH_];
__device__ __align__(256) __nv_bfloat16 g_hbh[B_ * UH_], g_hbl[B_ * UH_];
__device__ __align__(256) __nv_bfloat16 g_ctxh[B_ * UCV], g_ctxl[B_ * UCV];
__device__ __align__(256) __nv_bfloat16 g_Wxh[U_ * IVP * H3_], g_Wxl[U_ * IVP * H3_];
__device__ __align__(256) __nv_bfloat16 g_Whh[U_ * H_ * H3_], g_Whl[U_ * H_ * H3_];
__device__ __align__(256) __nv_bfloat16 g_Wqkvh[U_ * H_ * QKVN], g_Wqkvl[U_ * H_ * QKVN];
__device__ __align__(256) __nv_bfloat16 g_Woh[U_ * CHCV * CV_], g_Wol[U_ * CHCV * CV_];

// ---------------- small helpers ------------------------------------------
__device__ __forceinline__ void split2(float a, __nv_bfloat16& h, __nv_bfloat16& l) {
    h = __float2bfloat16(a);
    l = __float2bfloat16(a - __bfloat162float(h));
}
__device__ __forceinline__ unsigned sptr(const void* p) {
    return (unsigned)__cvta_generic_to_shared(p);
}
__device__ __forceinline__ void cpa16(void* dst, const void* src) {
    asm volatile("cp.async.cg.shared.global [%0], [%1], 16;\n"
                 :: "r"(sptr(dst)), "l"(src));
}
__device__ __forceinline__ void cp_commit() {
    asm volatile("cp.async.commit_group;\n");
}
template <int N> __device__ __forceinline__ void cp_wait() {
    asm volatile("cp.async.wait_group %0;\n" :: "n"(N));
}
__device__ __forceinline__ void ldsm4(unsigned addr, unsigned& r0, unsigned& r1,
                                      unsigned& r2, unsigned& r3) {
    asm volatile("ldmatrix.sync.aligned.m8n8.x4.shared.b16 {%0,%1,%2,%3}, [%4];\n"
                 : "=r"(r0), "=r"(r1), "=r"(r2), "=r"(r3) : "r"(addr));
}
__device__ __forceinline__ void ldsm4t(unsigned addr, unsigned& r0, unsigned& r1,
                                       unsigned& r2, unsigned& r3) {
    asm volatile("ldmatrix.sync.aligned.m8n8.x4.trans.shared.b16 {%0,%1,%2,%3}, [%4];\n"
                 : "=r"(r0), "=r"(r1), "=r"(r2), "=r"(r3) : "r"(addr));
}
__device__ __forceinline__ void mma16816(float* d, const unsigned* a, const unsigned* b) {
    asm volatile("mma.sync.aligned.m16n8k16.row.col.f32.bf16.bf16.f32 "
                 "{%0,%1,%2,%3}, {%4,%5,%6,%7}, {%8,%9}, {%0,%1,%2,%3};\n"
                 : "+f"(d[0]), "+f"(d[1]), "+f"(d[2]), "+f"(d[3])
                 : "r"(a[0]), "r"(a[1]), "r"(a[2]), "r"(a[3]),
                   "r"(b[0]), "r"(b[1]));
}

// ---------------- tensor-core GEMM (bf16x3 hi/lo split) ------------------
// C[M=4096, N] = Afp32 * Wfp32 computed as Ah*Bh + Ah*Bl + Al*Bh, fp32 acc.
// 128x128x16 block tile, 256 thr (8 warps, 64x32 warp tiles).
// 3-stage cp.async pipeline, ONE __syncthreads per k16 iteration.
enum { EPI_NONE = 0, EPI_BIAS = 1, EPI_GX = 2, EPI_FINAL = 3, EPI_SPLITV = 4 };

constexpr int APITCH = 48;                    // bytes per A smem row (32B data + 16 pad)
constexpr int BPITCH = 304;                   // bytes per B smem row (256B data + 48 pad)
constexpr int A_ST   = 128 * APITCH;          // 6144
constexpr int B_ST   = 16 * BPITCH;           // 4864
constexpr int STG_B  = 2 * A_ST + 2 * B_ST;   // 22016 per stage
constexpr int NSTAGE = 3;
constexpr int SMEM_DYN = NSTAGE * STG_B;      // 66048 bytes

template <int EPI>
__device__ __forceinline__ void tgemm_core(
    int N, int Kd,
    const __nv_bfloat16* __restrict__ Ah, const __nv_bfloat16* __restrict__ Al,
    int lda, long aBatch,
    const __nv_bfloat16* __restrict__ Bh, const __nv_bfloat16* __restrict__ Bl,
    long wBatch,
    float* __restrict__ C, int ldc, long cBatch,
    const float* __restrict__ e0, const float* __restrict__ e1,
    const float* __restrict__ e2, const float* __restrict__ e3)
{
    const int z = blockIdx.z;
    Ah += (long)z * aBatch;  Al += (long)z * aBatch;
    Bh += (long)z * wBatch;  Bl += (long)z * wBatch;
    C  += (long)z * cBatch;
    const int bm = blockIdx.y * 128;
    const int bn = blockIdx.x * 128;

    extern __shared__ __align__(16) char smem[];

    const int t = threadIdx.x, lane = t & 31, wid = t >> 5;
    const int wm = wid >> 2, wn = wid & 3;    // warp grid 2(m) x 4(n)

    auto sA = [&](int s, int arr) -> char* { return smem + s * STG_B + arr * A_ST; };
    auto sB = [&](int s, int arr) -> char* { return smem + s * STG_B + 2 * A_ST + arr * B_ST; };

    auto issue = [&](int kt, int s) {
#pragma unroll
        for (int i = 0; i < 2; i++) {               // A: 512 16B-chunks
            const int id = t + i * 256;
            const int arr = id >> 8, rem = id & 255;
            const int row = rem >> 1, ch = rem & 1;
            const __nv_bfloat16* src =
                (arr ? Al : Ah) + (long)(bm + row) * lda + kt * 16 + ch * 8;
            cpa16(sA(s, arr) + row * APITCH + ch * 16, src);
        }
#pragma unroll
        for (int i = 0; i < 2; i++) {               // B: 512 16B-chunks
            const int id = t + i * 256;
            const int arr = id >> 8, rem = id & 255;
            const int row = rem >> 4, ch = rem & 15;
            const __nv_bfloat16* src =
                (arr ? Bl : Bh) + (long)(kt * 16 + row) * N + bn + ch * 8;
            cpa16(sB(s, arr) + row * BPITCH + ch * 16, src);
        }
        cp_commit();
    };

    float acc[4][4][4];
#pragma unroll
    for (int mi = 0; mi < 4; mi++)
#pragma unroll
        for (int ni = 0; ni < 4; ni++)
#pragma unroll
            for (int r = 0; r < 4; r++) acc[mi][ni][r] = 0.f;

    const int KT = Kd / 16;                   // always >= 3 here
    issue(0, 0);
    issue(1, 1);

    for (int kt = 0; kt < KT; kt++) {
        cp_wait<1>();                         // stage kt resident
        __syncthreads();                      // everyone done reading stage kt-1 (== slot being refilled)
        if (kt + 2 < KT) issue(kt + 2, (kt + 2) % NSTAGE);
        const int s = kt % NSTAGE;

        unsigned Af[2][4][4];                 // [hi/lo][m-atom][reg]
#pragma unroll
        for (int hl = 0; hl < 2; hl++) {
            char* base = sA(s, hl);
#pragma unroll
            for (int mi = 0; mi < 4; mi++) {
                unsigned addr = sptr(base + (wm * 64 + mi * 16 + (lane & 15)) * APITCH
                                     + ((lane >> 4) << 4));
                ldsm4(addr, Af[hl][mi][0], Af[hl][mi][1], Af[hl][mi][2], Af[hl][mi][3]);
            }
        }
        unsigned Bf[2][4][2];                 // [hi/lo][n-atom][reg]
#pragma unroll
        for (int hl = 0; hl < 2; hl++) {
            char* base = sB(s, hl);
#pragma unroll
            for (int p = 0; p < 2; p++) {
                const int krow = (lane & 7) + ((lane >> 3) & 1) * 8;
                unsigned addr = sptr(base + krow * BPITCH + (wn * 32 + p * 16) * 2
                                     + ((lane >> 4) << 4));
                unsigned r0, r1, r2, r3;
                ldsm4t(addr, r0, r1, r2, r3);
                Bf[hl][2 * p][0] = r0;     Bf[hl][2 * p][1] = r1;
                Bf[hl][2 * p + 1][0] = r2; Bf[hl][2 * p + 1][1] = r3;
            }
        }
#pragma unroll
        for (int mi = 0; mi < 4; mi++)
#pragma unroll
            for (int ni = 0; ni < 4; ni++) {
                mma16816(acc[mi][ni], Af[0][mi], Bf[0][ni]);   // hi*hi
                mma16816(acc[mi][ni], Af[0][mi], Bf[1][ni]);   // hi*lo
                mma16816(acc[mi][ni], Af[1][mi], Bf[0][ni]);   // lo*hi
            }
        // no trailing sync: next iteration's barrier protects slot reuse
    }

    // epilogue: fragment (r) maps to m += (r&2)?8:0, n += r&1 -> float2 stores
#pragma unroll
    for (int mi = 0; mi < 4; mi++) {
#pragma unroll
        for (int half = 0; half < 2; half++) {
            const int m = bm + wm * 64 + mi * 16 + (lane >> 2) + half * 8;
            // per-row epilogue scalars
            float mk = 0.f, s0 = 0.f, s1 = 0.f;
            if (EPI == EPI_GX) {
                const long bu = (long)m * U_ + z;
                mk = e2[bu]; s0 = e0[bu]; s1 = e1[bu];
            } else if (EPI == EPI_FINAL) {
                const long bu = (long)m * U_ + z;
                mk = e2[bu];
            }
#pragma unroll
            for (int ni = 0; ni < 4; ni++) {
                const int n = bn + wn * 32 + ni * 8 + (lane & 3) * 2;
                float v0 = acc[mi][ni][half * 2 + 0];
                float v1 = acc[mi][ni][half * 2 + 1];
                if (EPI == EPI_GX) {
                    v0 = mk * (s0 * v0 + s1 * e3[(long)z * H3_ + n]);
                    v1 = mk * (s0 * v1 + s1 * e3[(long)z * H3_ + n + 1]);
                } else if (EPI == EPI_FINAL) {
                    const long idx = ((long)m * U_ + z) * H_ + n;
                    v0 = mk * (v0 + e0[idx])     + (1.f - mk) * e1[idx];
                    v1 = mk * (v1 + e0[idx + 1]) + (1.f - mk) * e1[idx + 1];
                }
                *reinterpret_cast<float2*>(C + (long)m * ldc + n) = make_float2(v0, v1);
            }
        }
    }
}

__global__ __launch_bounds__(256) void tg_gx() {
    tgemm_core<EPI_GX>(H3_, IVP, g_v0h, g_v0l, IVP, 0,
                       g_Wxh, g_Wxl, (long)IVP * H3_,
                       g_gx, U_ * H3_, H3_, g_p0, g_p1, g_mask, g_bvWx);
}
__global__ __launch_bounds__(256) void tg_gh() {
    tgemm_core<EPI_NONE>(H3_, H_, g_hsh, g_hsl, UH_, H_,
                         g_Whh, g_Whl, (long)H_ * H3_,
                         g_gh, U_ * H3_, H3_, nullptr, nullptr, nullptr, nullptr);
}
__global__ __launch_bounds__(256) void tg_qkv() {
    tgemm_core<EPI_NONE>(QKVN, H_, g_hbh, g_hbl, UH_, H_,
                         g_Wqkvh, g_Wqkvl, (long)H_ * QKVN,
                         g_qkv, U_ * QKVN, QKVN, nullptr, nullptr, nullptr, nullptr);
}
__global__ __launch_bounds__(256) void tg_out(const float* hs, float* out) {
    tgemm_core<EPI_FINAL>(H_, CHCV, g_ctxh, g_ctxl, UCV, CHCV,
                          g_Woh, g_Wol, (long)CHCV * H_,
                          out, U_ * H_, H_, g_hb, hs, g_mask, nullptr);
}

// ---------------- scalar fp32 SGEMM (small stage-1 GEMMs) ----------------
template <int EPI>
__device__ __forceinline__ void gemm_core(
    int N, int Kd,
    const float* __restrict__ A, int lda, int aBatch,
    const float* __restrict__ W, int wBatch,
    float* __restrict__ C, int ldc, int cBatch,
    const float* __restrict__ e0)
{
    const int z = blockIdx.z;
    A += (long)z * aBatch;
    W += (long)z * wBatch;
    if (EPI != EPI_SPLITV) C += (long)z * cBatch;
    const int bm = blockIdx.y * 128;
    const int bn = blockIdx.x * 128;

    __shared__ __align__(16) float As[8][128];
    __shared__ __align__(16) float Bs[8][128];

    const int tid  = threadIdx.x;
    const int tx   = tid & 15;
    const int ty   = tid >> 4;
    const int arow = tid >> 1;
    const int acol = (tid & 1) * 4;
    const int brow = tid >> 5;
    const int bcol = (tid & 31) * 4;
    const int gn   = bn + bcol;

    float acc[8][8];
#pragma unroll
    for (int i = 0; i < 8; i++)
#pragma unroll
        for (int j = 0; j < 8; j++) acc[i][j] = 0.f;

    float4 aReg = *reinterpret_cast<const float4*>(A + (long)(bm + arow) * lda + acol);
    float4 bReg = make_float4(0.f, 0.f, 0.f, 0.f);
    if (gn < N) bReg = *reinterpret_cast<const float4*>(W + (long)brow * N + gn);

    for (int k0 = 0; k0 < Kd; k0 += 8) {
        As[acol + 0][arow] = aReg.x;
        As[acol + 1][arow] = aReg.y;
        As[acol + 2][arow] = aReg.z;
        As[acol + 3][arow] = aReg.w;
        *reinterpret_cast<float4*>(&Bs[brow][bcol]) = bReg;
        __syncthreads();

        const int kn = k0 + 8;
        if (kn < Kd) {
            aReg = *reinterpret_cast<const float4*>(A + (long)(bm + arow) * lda + kn + acol);
            if (gn < N)
                bReg = *reinterpret_cast<const float4*>(W + (long)(kn + brow) * N + gn);
        }
#pragma unroll
        for (int kk = 0; kk < 8; kk++) {
            float4 aLo = *reinterpret_cast<const float4*>(&As[kk][ty * 4]);
            float4 aHi = *reinterpret_cast<const float4*>(&As[kk][64 + ty * 4]);
            float4 bLo = *reinterpret_cast<const float4*>(&Bs[kk][tx * 4]);
            float4 bHi = *reinterpret_cast<const float4*>(&Bs[kk][64 + tx * 4]);
            float a[8] = {aLo.x, aLo.y, aLo.z, aLo.w, aHi.x, aHi.y, aHi.z, aHi.w};
            float b[8] = {bLo.x, bLo.y, bLo.z, bLo.w, bHi.x, bHi.y, bHi.z, bHi.w};
#pragma unroll
            for (int i = 0; i < 8; i++)
#pragma unroll
                for (int j = 0; j < 8; j++)
                    acc[i][j] = fmaf(a[i], b[j], acc[i][j]);
        }
        __syncthreads();
    }

#pragma unroll
    for (int i = 0; i < 8; i++) {
        const int m = bm + ((i < 4) ? (ty * 4 + i) : (64 + ty * 4 + i - 4));
#pragma unroll
        for (int j = 0; j < 8; j++) {
            const int n = bn + ((j < 4) ? (tx * 4 + j) : (64 + tx * 4 + j - 4));
            if (n < N) {
                float v = acc[i][j];
                if (EPI == EPI_BIAS) {
                    v += e0[n];
                    C[(long)m * ldc + n] = v;
                } else if (EPI == EPI_SPLITV) {
                    v += e0[n];                            // bias
                    __nv_bfloat16 h, l; split2(v, h, l);   // fused v0 split (K-padded)
                    const long idx = (long)m * IVP + n;
                    g_v0h[idx] = h; g_v0l[idx] = l;
                } else {
                    C[(long)m * ldc + n] = v;
                }
            }
        }
    }
}

__global__ __launch_bounds__(256) void gemm_xk(const float* x, const float* Wk, const float* bk) {
    gemm_core<EPI_BIAS>(IK_, I_, x, I_, 0, Wk, 0, g_k0, IK_, 0, bk);
}
__global__ __launch_bounds__(256) void gemm_xv(const float* x, const float* Wv, const float* bv) {
    gemm_core<EPI_SPLITV>(IV_, I_, x, I_, 0, Wv, 0, nullptr, 0, 0, bv);
}
__global__ __launch_bounds__(256) void gemm_ql(const float* hs, const float* Wq) {
    gemm_core<EPI_NONE>(IK_, H_, hs, U_ * H_, H_, Wq, H_ * IK_,
                        g_ql, U_ * IK_, IK_, nullptr);
}

// ---------------- scores / 2-way softmax / top-4 mask --------------------
__global__ void score_kernel(const float* __restrict__ bk) {
    const int b = blockIdx.x, t = threadIdx.x;
    const int u = t >> 5, lane = t & 31;
    __shared__ float s0s[U_], s1s[U_];

    const float* ql = g_ql + (long)b * U_ * IK_ + u * IK_;
    const float* k0 = g_k0 + (long)b * IK_;
    float a0 = ql[lane] * k0[lane] + ql[lane + 32] * k0[lane + 32];
    float a1 = ql[lane] * bk[lane] + ql[lane + 32] * bk[lane + 32];
#pragma unroll
    for (int off = 16; off; off >>= 1) {
        a0 += __shfl_xor_sync(0xffffffffu, a0, off);
        a1 += __shfl_xor_sync(0xffffffffu, a1, off);
    }
    if (lane == 0) { s0s[u] = a0; s1s[u] = a1; }
    __syncthreads();

    if (t < U_) {
        const float s0 = s0s[t] * 0.125f;
        const float s1 = s1s[t] * 0.125f;
        const float m  = fmaxf(s0, s1);
        const float e0 = expf(s0 - m), e1 = expf(s1 - m);
        const float inv = 1.f / (e0 + e1);
        g_p0[b * U_ + t] = e0 * inv;
        g_p1[b * U_ + t] = e1 * inv;
        int rank = 0;
        const float me = s0s[t];
        for (int w = 0; w < U_; w++) {
            const float o = s0s[w];
            if (o > me || (o == me && w < t)) rank++;
        }
        g_mask[b * U_ + t] = (rank < KTOP) ? 1.f : 0.f;
    }
}

// ---------------- blend GRU weights (fused hi/lo split) ------------------
__global__ void blend_kernel(const float* __restrict__ src,
                             const float* __restrict__ sw, int which) {
    if (which == 0) {
        const long per_u = (long)IV_ * H3_;
        const long t = (long)blockIdx.x * blockDim.x + threadIdx.x;
        if (t >= U_ * per_u) return;
        const long u = t / per_u, r = t % per_u;
        const int  row = (int)(r / H3_), c = (int)(r % H3_);
        float acc = 0.f;
#pragma unroll
        for (int s = 0; s < NS_; s++)
            acc = fmaf(sw[u * NS_ + s], src[s * per_u + r], acc);
        g_Wx[t] = acc;                       // fp32 for bvwx
        __nv_bfloat16 h, l; split2(acc, h, l);
        const long idx = ((long)u * IVP + row) * H3_ + c;  // K-padded layout
        g_Wxh[idx] = h; g_Wxl[idx] = l;
    } else {
        const long per_u = (long)H_ * H3_;
        const long t = (long)blockIdx.x * blockDim.x + threadIdx.x;
        if (t >= U_ * per_u) return;
        const long u = t / per_u, r = t % per_u;
        float acc = 0.f;
#pragma unroll
        for (int s = 0; s < NS_; s++)
            acc = fmaf(sw[u * NS_ + s], src[s * per_u + r], acc);
        __nv_bfloat16 h, l; split2(acc, h, l);
        g_Whh[t] = h; g_Whl[t] = l;
    }
}

// bvWx[u,o] = sum_i bv[i] * Wx[u,i,o]
__global__ void bvwx_kernel(const float* __restrict__ bv) {
    const int t = blockIdx.x * blockDim.x + threadIdx.x;
    if (t >= U_ * H3_) return;
    const int u = t / H3_, o = t % H3_;
    const float* w = g_Wx + (long)u * IV_ * H3_ + o;
    float s = 0.f;
    for (int i = 0; i < IV_; i++) s = fmaf(bv[i], w[(long)i * H3_], s);
    g_bvWx[t] = s;
}

// ---------------- split kernels ------------------------------------------
__global__ void split_hs(const float* __restrict__ hs) {
    const long t = (long)blockIdx.x * blockDim.x + threadIdx.x;
    __nv_bfloat16 h, l; split2(hs[t], h, l);
    g_hsh[t] = h; g_hsl[t] = l;
}
__global__ void split_wo(const float* __restrict__ Wo) {
    const long t = (long)blockIdx.x * blockDim.x + threadIdx.x;
    __nv_bfloat16 h, l; split2(Wo[t], h, l);
    g_Woh[t] = h; g_Wol[t] = l;
}

// ---------------- GRU pointwise (fused hi/lo split of hb) ----------------
__global__ void gru_kernel(const float* __restrict__ hs) {
    const long t = (long)blockIdx.x * blockDim.x + threadIdx.x;
    if (t >= (long)B_ * U_ * H_) return;
    const long bu = t / H_;
    const int  h  = (int)(t % H_);
    const float* gx = g_gx + bu * H3_;
    const float* gh = g_gh + bu * H3_;
    const float xr = gx[h], xz = gx[H_ + h], xn = gx[2 * H_ + h];
    const float hr = gh[h], hz = gh[H_ + h], hn = gh[2 * H_ + h];
    const float r = 1.f / (1.f + expf(-(xr + hr)));
    const float z = 1.f / (1.f + expf(-(xz + hz)));
    const float n = tanhf(fmaf(r, hn, xn));
    const float hy = n + z * (hs[t] - n);
    g_hb[t] = hy;
    __nv_bfloat16 hh, hl; split2(hy, hh, hl);
    g_hbh[t] = hh; g_hbl[t] = hl;
}

// ---------------- pack [Wq_|Wk_|Wv_] -> Wqkv hi/lo -----------------------
__global__ void pack_kernel(const float* __restrict__ Wq_,
                            const float* __restrict__ Wk_,
                            const float* __restrict__ Wv_) {
    const long t = (long)blockIdx.x * blockDim.x + threadIdx.x;
    if (t >= (long)U_ * H_ * QKVN) return;
    const long u = t / ((long)H_ * QKVN);
    const long r = t % ((long)H_ * QKVN);
    const int  k = (int)(r / QKVN);
    const int  n = (int)(r % QKVN);
    float v;
    if (n < 128)       v = Wq_[((long)u * H_ + k) * 128 + n];
    else if (n < 256)  v = Wk_[((long)u * H_ + k) * 128 + (n - 128)];
    else               v = Wv_[((long)u * H_ + k) * CHCV + (n - 256)];
    __nv_bfloat16 h, l; split2(v, h, l);
    g_Wqkvh[t] = h; g_Wqkvl[t] = l;
}

// ---------------- tiny 4-head, 6x6 attention (fused ctx split) -----------
__global__ void attn_kernel() {
    const int b = blockIdx.x, t = threadIdx.x;
    __shared__ float qs[U_ * 128];
    __shared__ float ks[U_ * 128];
    __shared__ float att_s[CH_ * U_ * U_];
    __shared__ float ap[CH_ * U_ * U_];
    __shared__ float msk[U_];

    const float* base = g_qkv + (long)b * U_ * QKVN;
    for (int i = t; i < U_ * 256; i += 256) {
        const int u = i / 256, c = i % 256;
        const float v = base[u * QKVN + c];
        if (c < 128) qs[u * 128 + c] = v;
        else         ks[u * 128 + (c - 128)] = v;
    }
    if (t < U_) msk[t] = g_mask[b * U_ + t];
    __syncthreads();

    if (t < CH_ * U_ * U_) {
        const int ch = t / 36, rq = (t / 6) % 6, rk = t % 6;
        const float* qp = &qs[rq * 128 + ch * CK_];
        const float* kp = &ks[rk * 128 + ch * CK_];
        float s = 0.f;
#pragma unroll
        for (int ck = 0; ck < CK_; ck++) s = fmaf(qp[ck], kp[ck], s);
        att_s[t] = s * 0.17677669529663687f;
    }
    __syncthreads();

    if (t < CH_ * U_) {
        const int ch = t / U_, rq = t % U_;
        const float* row = &att_s[(ch * U_ + rq) * U_];
        float m = row[0];
#pragma unroll
        for (int k = 1; k < U_; k++) m = fmaxf(m, row[k]);
        float e[U_]; float sum = 0.f;
#pragma unroll
        for (int k = 0; k < U_; k++) { e[k] = expf(row[k] - m); sum += e[k]; }
        const float inv = msk[rq] / sum;
#pragma unroll
        for (int k = 0; k < U_; k++) ap[(ch * U_ + rq) * U_ + k] = e[k] * inv;
    }
    __syncthreads();

    const long cb = (long)b * U_ * CHCV;
    for (int o = t; o < U_ * CHCV; o += 256) {
        const int uq = o / CHCV;
        const int r  = o % CHCV;
        const int ch = r / CV_;
        float s = 0.f;
#pragma unroll
        for (int k = 0; k < U_; k++)
            s = fmaf(ap[(ch * U_ + uq) * U_ + k], base[k * QKVN + 256 + r], s);
        __nv_bfloat16 h, l; split2(s, h, l);
        g_ctxh[cb + o] = h; g_ctxl[cb + o] = l;
    }
}

// ---------------- launch -------------------------------------------------
extern "C" void kernel_launch(void* const* d_in, const int* in_sizes, int n_in,
                              void* d_out, int out_size) {
    (void)in_sizes; (void)n_in; (void)out_size;
    const float* x    = (const float*)d_in[0];
    const float* hs   = (const float*)d_in[1];
    const float* Wk   = (const float*)d_in[2];
    const float* bk   = (const float*)d_in[3];
    const float* Wv   = (const float*)d_in[4];
    const float* bv   = (const float*)d_in[5];
    const float* Wq   = (const float*)d_in[6];
    const float* Wq_p = (const float*)d_in[7];
    const float* Wk_p = (const float*)d_in[8];
    const float* Wv_p = (const float*)d_in[9];
    const float* Wo   = (const float*)d_in[10];
    const float* sw   = (const float*)d_in[11];
    const float* gwx  = (const float*)d_in[12];
    const float* gwh  = (const float*)d_in[13];
    float* out = (float*)d_out;

    // allow 66KB dynamic smem on the tensor GEMMs (idempotent host calls)
    cudaFuncSetAttribute(tg_gx,  cudaFuncAttributeMaxDynamicSharedMemorySize, SMEM_DYN);
    cudaFuncSetAttribute(tg_gh,  cudaFuncAttributeMaxDynamicSharedMemorySize, SMEM_DYN);
    cudaFuncSetAttribute(tg_qkv, cudaFuncAttributeMaxDynamicSharedMemorySize, SMEM_DYN);
    cudaFuncSetAttribute(tg_out, cudaFuncAttributeMaxDynamicSharedMemorySize, SMEM_DYN);

    // stage 1: projections + scores (+ independent preprocessing)
    gemm_xk<<<dim3(1, 32, 1), 256>>>(x, Wk, bk);
    gemm_xv<<<dim3(4, 32, 1), 256>>>(x, Wv, bv);   // fused v0 hi/lo split
    gemm_ql<<<dim3(1, 32, U_), 256>>>(hs, Wq);
    score_kernel<<<B_, 192>>>(bk);
    split_hs<<<(B_ * UH_) / 256, 256>>>(hs);
    split_wo<<<(U_ * CHCV * CV_) / 256, 256>>>(Wo);
    pack_kernel<<<(U_ * H_ * QKVN) / 256, 256>>>(Wq_p, Wk_p, Wv_p);
    blend_kernel<<<(U_ * IV_ * H3_) / 256, 256>>>(gwx, sw, 0);
    blend_kernel<<<(U_ * H_ * H3_) / 256, 256>>>(gwh, sw, 1);
    bvwx_kernel<<<(U_ * H3_ + 255) / 256, 256>>>(bv);

    // stage 2: GRU gates (tensor) + hidden update
    tg_gx<<<dim3(H3_ / 128, 32, U_), 256, SMEM_DYN>>>();
    tg_gh<<<dim3(H3_ / 128, 32, U_), 256, SMEM_DYN>>>();
    gru_kernel<<<(B_ * U_ * H_) / 256, 256>>>(hs);

    // stage 3: qkv (tensor) + attention + output projection (tensor, fused blend)
    tg_qkv<<<dim3(QKVN / 128, 32, U_), 256, SMEM_DYN>>>();
    attn_kernel<<<B_, 256>>>();
    tg_out<<<dim3(H_ / 128, 32, U_), 256, SMEM_DYN>>>(hs, out);
}

// round 16
// speedup vs baseline: 1.0036x; 1.0036x over previous
#include <cuda_runtime.h>
#include <cuda_bf16.h>
#include <math.h>

// ---------------- problem constants ----------------
constexpr int B_   = 4096;
constexpr int U_   = 6;
constexpr int I_   = 1024;
constexpr int H_   = 512;
constexpr int IK_  = 64;
constexpr int IV_  = 400;
constexpr int IVP  = 416;                     // IV padded to mult of 16
constexpr int KTOP = 4;
constexpr int CH_  = 4;
constexpr int CK_  = 32;
constexpr int CV_  = 512;
constexpr int NS_  = 4;
constexpr int H3_  = 3 * H_;                  // 1536
constexpr int CHCV = CH_ * CV_;               // 2048
constexpr int QKVN = CH_*CK_ + CH_*CK_ + CHCV; // 2304
constexpr int UH_  = U_ * H_;                 // 3072
constexpr int UCV  = U_ * CHCV;               // 12288

// ---------------- fp32 scratch ----------------
__device__ __align__(256) float g_k0[B_ * IK_];
__device__ __align__(256) float g_ql[B_ * U_ * IK_];
__device__ __align__(256) float g_p0[B_ * U_];
__device__ __align__(256) float g_p1[B_ * U_];
__device__ __align__(256) float g_mask[B_ * U_];
__device__ __align__(256) float g_Wx[U_ * IV_ * H3_];     // fp32 kept for bvwx
__device__ __align__(256) float g_bvWx[U_ * H3_];
__device__ __align__(256) float g_gx[B_ * U_ * H3_];
__device__ __align__(256) float g_gh[B_ * U_ * H3_];
__device__ __align__(256) float g_hb[B_ * U_ * H_];
__device__ __align__(256) float g_qkv[B_ * U_ * QKVN];

// ---------------- bf16 hi/lo scratch (zero-init covers K padding) --------
__device__ __align__(256) __nv_bfloat16 g_v0h[B_ * IVP], g_v0l[B_ * IVP];
__device__ __align__(256) __nv_bfloat16 g_hsh[B_ * UH_], g_hsl[B_ * UH_];
__device__ __align__(256) __nv_bfloat16 g_hbh[B_ * UH_], g_hbl[B_ * UH_];
__device__ __align__(256) __nv_bfloat16 g_ctxh[B_ * UCV], g_ctxl[B_ * UCV];
__device__ __align__(256) __nv_bfloat16 g_Wxh[U_ * IVP * H3_], g_Wxl[U_ * IVP * H3_];
__device__ __align__(256) __nv_bfloat16 g_Whh[U_ * H_ * H3_], g_Whl[U_ * H_ * H3_];
__device__ __align__(256) __nv_bfloat16 g_Wqkvh[U_ * H_ * QKVN], g_Wqkvl[U_ * H_ * QKVN];
__device__ __align__(256) __nv_bfloat16 g_Woh[U_ * CHCV * CV_], g_Wol[U_ * CHCV * CV_];

// ---------------- small helpers ------------------------------------------
__device__ __forceinline__ void split2(float a, __nv_bfloat16& h, __nv_bfloat16& l) {
    h = __float2bfloat16(a);
    l = __float2bfloat16(a - __bfloat162float(h));
}
__device__ __forceinline__ unsigned sptr(const void* p) {
    return (unsigned)__cvta_generic_to_shared(p);
}
__device__ __forceinline__ void cpa16(void* dst, const void* src) {
    asm volatile("cp.async.cg.shared.global [%0], [%1], 16;\n"
                 :: "r"(sptr(dst)), "l"(src));
}
__device__ __forceinline__ void cp_commit() {
    asm volatile("cp.async.commit_group;\n");
}
template <int N> __device__ __forceinline__ void cp_wait() {
    asm volatile("cp.async.wait_group %0;\n" :: "n"(N));
}
__device__ __forceinline__ void ldsm4(unsigned addr, unsigned& r0, unsigned& r1,
                                      unsigned& r2, unsigned& r3) {
    asm volatile("ldmatrix.sync.aligned.m8n8.x4.shared.b16 {%0,%1,%2,%3}, [%4];\n"
                 : "=r"(r0), "=r"(r1), "=r"(r2), "=r"(r3) : "r"(addr));
}
__device__ __forceinline__ void ldsm4t(unsigned addr, unsigned& r0, unsigned& r1,
                                       unsigned& r2, unsigned& r3) {
    asm volatile("ldmatrix.sync.aligned.m8n8.x4.trans.shared.b16 {%0,%1,%2,%3}, [%4];\n"
                 : "=r"(r0), "=r"(r1), "=r"(r2), "=r"(r3) : "r"(addr));
}
__device__ __forceinline__ void mma16816(float* d, const unsigned* a, const unsigned* b) {
    asm volatile("mma.sync.aligned.m16n8k16.row.col.f32.bf16.bf16.f32 "
                 "{%0,%1,%2,%3}, {%4,%5,%6,%7}, {%8,%9}, {%0,%1,%2,%3};\n"
                 : "+f"(d[0]), "+f"(d[1]), "+f"(d[2]), "+f"(d[3])
                 : "r"(a[0]), "r"(a[1]), "r"(a[2]), "r"(a[3]),
                   "r"(b[0]), "r"(b[1]));
}

// ---------------- tensor-core GEMM (bf16x3 hi/lo split) ------------------
// C[M=4096, N] = Afp32 * Wfp32 computed as Ah*Bh + Ah*Bl + Al*Bh, fp32 acc.
// 128x128x16 block tile, 256 thr (8 warps, 64x32 warp tiles).
// 3-stage cp.async pipeline, ONE __syncthreads per k16 iteration.
enum { EPI_NONE = 0, EPI_BIAS = 1, EPI_GX = 2, EPI_FINAL = 3, EPI_SPLITV = 4 };

constexpr int APITCH = 48;                    // bytes per A smem row (32B data + 16 pad)
constexpr int BPITCH = 304;                   // bytes per B smem row (256B data + 48 pad)
constexpr int A_ST   = 128 * APITCH;          // 6144
constexpr int B_ST   = 16 * BPITCH;           // 4864
constexpr int STG_B  = 2 * A_ST + 2 * B_ST;   // 22016 per stage
constexpr int NSTAGE = 3;
constexpr int SMEM_DYN = NSTAGE * STG_B;      // 66048 bytes

template <int EPI>
__device__ __forceinline__ void tgemm_core(
    int N, int Kd,
    const __nv_bfloat16* __restrict__ Ah, const __nv_bfloat16* __restrict__ Al,
    int lda, long aBatch,
    const __nv_bfloat16* __restrict__ Bh, const __nv_bfloat16* __restrict__ Bl,
    long wBatch,
    float* __restrict__ C, int ldc, long cBatch,
    const float* __restrict__ e0, const float* __restrict__ e1,
    const float* __restrict__ e2, const float* __restrict__ e3)
{
    const int z = blockIdx.z;
    Ah += (long)z * aBatch;  Al += (long)z * aBatch;
    Bh += (long)z * wBatch;  Bl += (long)z * wBatch;
    C  += (long)z * cBatch;
    const int bm = blockIdx.y * 128;
    const int bn = blockIdx.x * 128;

    extern __shared__ __align__(16) char smem[];

    const int t = threadIdx.x, lane = t & 31, wid = t >> 5;
    const int wm = wid >> 2, wn = wid & 3;    // warp grid 2(m) x 4(n)

    auto sA = [&](int s, int arr) -> char* { return smem + s * STG_B + arr * A_ST; };
    auto sB = [&](int s, int arr) -> char* { return smem + s * STG_B + 2 * A_ST + arr * B_ST; };

    auto issue = [&](int kt, int s) {
#pragma unroll
        for (int i = 0; i < 2; i++) {               // A: 512 16B-chunks
            const int id = t + i * 256;
            const int arr = id >> 8, rem = id & 255;
            const int row = rem >> 1, ch = rem & 1;
            const __nv_bfloat16* src =
                (arr ? Al : Ah) + (long)(bm + row) * lda + kt * 16 + ch * 8;
            cpa16(sA(s, arr) + row * APITCH + ch * 16, src);
        }
#pragma unroll
        for (int i = 0; i < 2; i++) {               // B: 512 16B-chunks
            const int id = t + i * 256;
            const int arr = id >> 8, rem = id & 255;
            const int row = rem >> 4, ch = rem & 15;
            const __nv_bfloat16* src =
                (arr ? Bl : Bh) + (long)(kt * 16 + row) * N + bn + ch * 8;
            cpa16(sB(s, arr) + row * BPITCH + ch * 16, src);
        }
        cp_commit();
    };

    float acc[4][4][4];
#pragma unroll
    for (int mi = 0; mi < 4; mi++)
#pragma unroll
        for (int ni = 0; ni < 4; ni++)
#pragma unroll
            for (int r = 0; r < 4; r++) acc[mi][ni][r] = 0.f;

    const int KT = Kd / 16;                   // always >= 3 here
    issue(0, 0);
    issue(1, 1);

    for (int kt = 0; kt < KT; kt++) {
        cp_wait<1>();                         // stage kt resident
        __syncthreads();                      // everyone done reading stage kt-1 (== slot being refilled)
        if (kt + 2 < KT) issue(kt + 2, (kt + 2) % NSTAGE);
        const int s = kt % NSTAGE;

        unsigned Af[2][4][4];                 // [hi/lo][m-atom][reg]
#pragma unroll
        for (int hl = 0; hl < 2; hl++) {
            char* base = sA(s, hl);
#pragma unroll
            for (int mi = 0; mi < 4; mi++) {
                unsigned addr = sptr(base + (wm * 64 + mi * 16 + (lane & 15)) * APITCH
                                     + ((lane >> 4) << 4));
                ldsm4(addr, Af[hl][mi][0], Af[hl][mi][1], Af[hl][mi][2], Af[hl][mi][3]);
            }
        }
        unsigned Bf[2][4][2];                 // [hi/lo][n-atom][reg]
#pragma unroll
        for (int hl = 0; hl < 2; hl++) {
            char* base = sB(s, hl);
#pragma unroll
            for (int p = 0; p < 2; p++) {
                const int krow = (lane & 7) + ((lane >> 3) & 1) * 8;
                unsigned addr = sptr(base + krow * BPITCH + (wn * 32 + p * 16) * 2
                                     + ((lane >> 4) << 4));
                unsigned r0, r1, r2, r3;
                ldsm4t(addr, r0, r1, r2, r3);
                Bf[hl][2 * p][0] = r0;     Bf[hl][2 * p][1] = r1;
                Bf[hl][2 * p + 1][0] = r2; Bf[hl][2 * p + 1][1] = r3;
            }
        }
#pragma unroll
        for (int mi = 0; mi < 4; mi++)
#pragma unroll
            for (int ni = 0; ni < 4; ni++) {
                mma16816(acc[mi][ni], Af[0][mi], Bf[0][ni]);   // hi*hi
                mma16816(acc[mi][ni], Af[0][mi], Bf[1][ni]);   // hi*lo
                mma16816(acc[mi][ni], Af[1][mi], Bf[0][ni]);   // lo*hi
            }
        // no trailing sync: next iteration's barrier protects slot reuse
    }

    // epilogue: fragment (r) maps to m += (r&2)?8:0, n += r&1 -> float2 stores
#pragma unroll
    for (int mi = 0; mi < 4; mi++) {
#pragma unroll
        for (int half = 0; half < 2; half++) {
            const int m = bm + wm * 64 + mi * 16 + (lane >> 2) + half * 8;
            // per-row epilogue scalars
            float mk = 0.f, s0 = 0.f, s1 = 0.f;
            if (EPI == EPI_GX) {
                const long bu = (long)m * U_ + z;
                mk = e2[bu]; s0 = e0[bu]; s1 = e1[bu];
            } else if (EPI == EPI_FINAL) {
                const long bu = (long)m * U_ + z;
                mk = e2[bu];
            }
#pragma unroll
            for (int ni = 0; ni < 4; ni++) {
                const int n = bn + wn * 32 + ni * 8 + (lane & 3) * 2;
                float v0 = acc[mi][ni][half * 2 + 0];
                float v1 = acc[mi][ni][half * 2 + 1];
                if (EPI == EPI_GX) {
                    v0 = mk * (s0 * v0 + s1 * e3[(long)z * H3_ + n]);
                    v1 = mk * (s0 * v1 + s1 * e3[(long)z * H3_ + n + 1]);
                } else if (EPI == EPI_FINAL) {
                    const long idx = ((long)m * U_ + z) * H_ + n;
                    v0 = mk * (v0 + e0[idx])     + (1.f - mk) * e1[idx];
                    v1 = mk * (v1 + e0[idx + 1]) + (1.f - mk) * e1[idx + 1];
                }
                *reinterpret_cast<float2*>(C + (long)m * ldc + n) = make_float2(v0, v1);
            }
        }
    }
}

__global__ __launch_bounds__(256) void tg_gx() {
    tgemm_core<EPI_GX>(H3_, IVP, g_v0h, g_v0l, IVP, 0,
                       g_Wxh, g_Wxl, (long)IVP * H3_,
                       g_gx, U_ * H3_, H3_, g_p0, g_p1, g_mask, g_bvWx);
}
__global__ __launch_bounds__(256) void tg_gh() {
    tgemm_core<EPI_NONE>(H3_, H_, g_hsh, g_hsl, UH_, H_,
                         g_Whh, g_Whl, (long)H_ * H3_,
                         g_gh, U_ * H3_, H3_, nullptr, nullptr, nullptr, nullptr);
}
__global__ __launch_bounds__(256) void tg_qkv() {
    tgemm_core<EPI_NONE>(QKVN, H_, g_hbh, g_hbl, UH_, H_,
                         g_Wqkvh, g_Wqkvl, (long)H_ * QKVN,
                         g_qkv, U_ * QKVN, QKVN, nullptr, nullptr, nullptr, nullptr);
}
__global__ __launch_bounds__(256) void tg_out(const float* hs, float* out) {
    tgemm_core<EPI_FINAL>(H_, CHCV, g_ctxh, g_ctxl, UCV, CHCV,
                          g_Woh, g_Wol, (long)CHCV * H_,
                          out, U_ * H_, H_, g_hb, hs, g_mask, nullptr);
}

// ---------------- scalar fp32 SGEMM (small stage-1 GEMMs) ----------------
template <int EPI>
__device__ __forceinline__ void gemm_core(
    int N, int Kd,
    const float* __restrict__ A, int lda, int aBatch,
    const float* __restrict__ W, int wBatch,
    float* __restrict__ C, int ldc, int cBatch,
    const float* __restrict__ e0)
{
    const int z = blockIdx.z;
    A += (long)z * aBatch;
    W += (long)z * wBatch;
    if (EPI != EPI_SPLITV) C += (long)z * cBatch;
    const int bm = blockIdx.y * 128;
    const int bn = blockIdx.x * 128;

    __shared__ __align__(16) float As[8][128];
    __shared__ __align__(16) float Bs[8][128];

    const int tid  = threadIdx.x;
    const int tx   = tid & 15;
    const int ty   = tid >> 4;
    const int arow = tid >> 1;
    const int acol = (tid & 1) * 4;
    const int brow = tid >> 5;
    const int bcol = (tid & 31) * 4;
    const int gn   = bn + bcol;

    float acc[8][8];
#pragma unroll
    for (int i = 0; i < 8; i++)
#pragma unroll
        for (int j = 0; j < 8; j++) acc[i][j] = 0.f;

    float4 aReg = *reinterpret_cast<const float4*>(A + (long)(bm + arow) * lda + acol);
    float4 bReg = make_float4(0.f, 0.f, 0.f, 0.f);
    if (gn < N) bReg = *reinterpret_cast<const float4*>(W + (long)brow * N + gn);

    for (int k0 = 0; k0 < Kd; k0 += 8) {
        As[acol + 0][arow] = aReg.x;
        As[acol + 1][arow] = aReg.y;
        As[acol + 2][arow] = aReg.z;
        As[acol + 3][arow] = aReg.w;
        *reinterpret_cast<float4*>(&Bs[brow][bcol]) = bReg;
        __syncthreads();

        const int kn = k0 + 8;
        if (kn < Kd) {
            aReg = *reinterpret_cast<const float4*>(A + (long)(bm + arow) * lda + kn + acol);
            if (gn < N)
                bReg = *reinterpret_cast<const float4*>(W + (long)(kn + brow) * N + gn);
        }
#pragma unroll
        for (int kk = 0; kk < 8; kk++) {
            float4 aLo = *reinterpret_cast<const float4*>(&As[kk][ty * 4]);
            float4 aHi = *reinterpret_cast<const float4*>(&As[kk][64 + ty * 4]);
            float4 bLo = *reinterpret_cast<const float4*>(&Bs[kk][tx * 4]);
            float4 bHi = *reinterpret_cast<const float4*>(&Bs[kk][64 + tx * 4]);
            float a[8] = {aLo.x, aLo.y, aLo.z, aLo.w, aHi.x, aHi.y, aHi.z, aHi.w};
            float b[8] = {bLo.x, bLo.y, bLo.z, bLo.w, bHi.x, bHi.y, bHi.z, bHi.w};
#pragma unroll
            for (int i = 0; i < 8; i++)
#pragma unroll
                for (int j = 0; j < 8; j++)
                    acc[i][j] = fmaf(a[i], b[j], acc[i][j]);
        }
        __syncthreads();
    }

#pragma unroll
    for (int i = 0; i < 8; i++) {
        const int m = bm + ((i < 4) ? (ty * 4 + i) : (64 + ty * 4 + i - 4));
#pragma unroll
        for (int j = 0; j < 8; j++) {
            const int n = bn + ((j < 4) ? (tx * 4 + j) : (64 + tx * 4 + j - 4));
            if (n < N) {
                float v = acc[i][j];
                if (EPI == EPI_BIAS) {
                    v += e0[n];
                    C[(long)m * ldc + n] = v;
                } else if (EPI == EPI_SPLITV) {
                    v += e0[n];                            // bias
                    __nv_bfloat16 h, l; split2(v, h, l);   // fused v0 split (K-padded)
                    const long idx = (long)m * IVP + n;
                    g_v0h[idx] = h; g_v0l[idx] = l;
                } else {
                    C[(long)m * ldc + n] = v;
                }
            }
        }
    }
}

__global__ __launch_bounds__(256) void gemm_xk(const float* x, const float* Wk, const float* bk) {
    gemm_core<EPI_BIAS>(IK_, I_, x, I_, 0, Wk, 0, g_k0, IK_, 0, bk);
}
__global__ __launch_bounds__(256) void gemm_xv(const float* x, const float* Wv, const float* bv) {
    gemm_core<EPI_SPLITV>(IV_, I_, x, I_, 0, Wv, 0, nullptr, 0, 0, bv);
}
__global__ __launch_bounds__(256) void gemm_ql(const float* hs, const float* Wq) {
    gemm_core<EPI_NONE>(IK_, H_, hs, U_ * H_, H_, Wq, H_ * IK_,
                        g_ql, U_ * IK_, IK_, nullptr);
}

// ---------------- scores / 2-way softmax / top-4 mask --------------------
__global__ void score_kernel(const float* __restrict__ bk) {
    const int b = blockIdx.x, t = threadIdx.x;
    const int u = t >> 5, lane = t & 31;
    __shared__ float s0s[U_], s1s[U_];

    const float* ql = g_ql + (long)b * U_ * IK_ + u * IK_;
    const float* k0 = g_k0 + (long)b * IK_;
    float a0 = ql[lane] * k0[lane] + ql[lane + 32] * k0[lane + 32];
    float a1 = ql[lane] * bk[lane] + ql[lane + 32] * bk[lane + 32];
#pragma unroll
    for (int off = 16; off; off >>= 1) {
        a0 += __shfl_xor_sync(0xffffffffu, a0, off);
        a1 += __shfl_xor_sync(0xffffffffu, a1, off);
    }
    if (lane == 0) { s0s[u] = a0; s1s[u] = a1; }
    __syncthreads();

    if (t < U_) {
        const float s0 = s0s[t] * 0.125f;
        const float s1 = s1s[t] * 0.125f;
        const float m  = fmaxf(s0, s1);
        const float e0 = expf(s0 - m), e1 = expf(s1 - m);
        const float inv = 1.f / (e0 + e1);
        g_p0[b * U_ + t] = e0 * inv;
        g_p1[b * U_ + t] = e1 * inv;
        int rank = 0;
        const float me = s0s[t];
        for (int w = 0; w < U_; w++) {
            const float o = s0s[w];
            if (o > me || (o == me && w < t)) rank++;
        }
        g_mask[b * U_ + t] = (rank < KTOP) ? 1.f : 0.f;
    }
}

// ---------------- blend GRU weights (fused hi/lo split) ------------------
__global__ void blend_kernel(const float* __restrict__ src,
                             const float* __restrict__ sw, int which) {
    if (which == 0) {
        const long per_u = (long)IV_ * H3_;
        const long t = (long)blockIdx.x * blockDim.x + threadIdx.x;
        if (t >= U_ * per_u) return;
        const long u = t / per_u, r = t % per_u;
        const int  row = (int)(r / H3_), c = (int)(r % H3_);
        float acc = 0.f;
#pragma unroll
        for (int s = 0; s < NS_; s++)
            acc = fmaf(sw[u * NS_ + s], src[s * per_u + r], acc);
        g_Wx[t] = acc;                       // fp32 for bvwx
        __nv_bfloat16 h, l; split2(acc, h, l);
        const long idx = ((long)u * IVP + row) * H3_ + c;  // K-padded layout
        g_Wxh[idx] = h; g_Wxl[idx] = l;
    } else {
        const long per_u = (long)H_ * H3_;
        const long t = (long)blockIdx.x * blockDim.x + threadIdx.x;
        if (t >= U_ * per_u) return;
        const long u = t / per_u, r = t % per_u;
        float acc = 0.f;
#pragma unroll
        for (int s = 0; s < NS_; s++)
            acc = fmaf(sw[u * NS_ + s], src[s * per_u + r], acc);
        __nv_bfloat16 h, l; split2(acc, h, l);
        g_Whh[t] = h; g_Whl[t] = l;
    }
}

// bvWx[u,o] = sum_i bv[i] * Wx[u,i,o]
__global__ void bvwx_kernel(const float* __restrict__ bv) {
    const int t = blockIdx.x * blockDim.x + threadIdx.x;
    if (t >= U_ * H3_) return;
    const int u = t / H3_, o = t % H3_;
    const float* w = g_Wx + (long)u * IV_ * H3_ + o;
    float s = 0.f;
    for (int i = 0; i < IV_; i++) s = fmaf(bv[i], w[(long)i * H3_], s);
    g_bvWx[t] = s;
}

// ---------------- split kernels ------------------------------------------
__global__ void split_hs(const float* __restrict__ hs) {
    const long t = (long)blockIdx.x * blockDim.x + threadIdx.x;
    __nv_bfloat16 h, l; split2(hs[t], h, l);
    g_hsh[t] = h; g_hsl[t] = l;
}
__global__ void split_wo(const float* __restrict__ Wo) {
    const long t = (long)blockIdx.x * blockDim.x + threadIdx.x;
    __nv_bfloat16 h, l; split2(Wo[t], h, l);
    g_Woh[t] = h; g_Wol[t] = l;
}

// ---------------- GRU pointwise (fused hi/lo split of hb) ----------------
__global__ void gru_kernel(const float* __restrict__ hs) {
    const long t = (long)blockIdx.x * blockDim.x + threadIdx.x;
    if (t >= (long)B_ * U_ * H_) return;
    const long bu = t / H_;
    const int  h  = (int)(t % H_);
    const float* gx = g_gx + bu * H3_;
    const float* gh = g_gh + bu * H3_;
    const float xr = gx[h], xz = gx[H_ + h], xn = gx[2 * H_ + h];
    const float hr = gh[h], hz = gh[H_ + h], hn = gh[2 * H_ + h];
    const float r = 1.f / (1.f + expf(-(xr + hr)));
    const float z = 1.f / (1.f + expf(-(xz + hz)));
    const float n = tanhf(fmaf(r, hn, xn));
    const float hy = n + z * (hs[t] - n);
    g_hb[t] = hy;
    __nv_bfloat16 hh, hl; split2(hy, hh, hl);
    g_hbh[t] = hh; g_hbl[t] = hl;
}

// ---------------- pack [Wq_|Wk_|Wv_] -> Wqkv hi/lo -----------------------
__global__ void pack_kernel(const float* __restrict__ Wq_,
                            const float* __restrict__ Wk_,
                            const float* __restrict__ Wv_) {
    const long t = (long)blockIdx.x * blockDim.x + threadIdx.x;
    if (t >= (long)U_ * H_ * QKVN) return;
    const long u = t / ((long)H_ * QKVN);
    const long r = t % ((long)H_ * QKVN);
    const int  k = (int)(r / QKVN);
    const int  n = (int)(r % QKVN);
    float v;
    if (n < 128)       v = Wq_[((long)u * H_ + k) * 128 + n];
    else if (n < 256)  v = Wk_[((long)u * H_ + k) * 128 + (n - 128)];
    else               v = Wv_[((long)u * H_ + k) * CHCV + (n - 256)];
    __nv_bfloat16 h, l; split2(v, h, l);
    g_Wqkvh[t] = h; g_Wqkvl[t] = l;
}

// ---------------- tiny 4-head, 6x6 attention (fused ctx split) -----------
__global__ void attn_kernel() {
    const int b = blockIdx.x, t = threadIdx.x;
    __shared__ float qs[U_ * 128];
    __shared__ float ks[U_ * 128];
    __shared__ float att_s[CH_ * U_ * U_];
    __shared__ float ap[CH_ * U_ * U_];
    __shared__ float msk[U_];

    const float* base = g_qkv + (long)b * U_ * QKVN;
    for (int i = t; i < U_ * 256; i += 256) {
        const int u = i / 256, c = i % 256;
        const float v = base[u * QKVN + c];
        if (c < 128) qs[u * 128 + c] = v;
        else         ks[u * 128 + (c - 128)] = v;
    }
    if (t < U_) msk[t] = g_mask[b * U_ + t];
    __syncthreads();

    if (t < CH_ * U_ * U_) {
        const int ch = t / 36, rq = (t / 6) % 6, rk = t % 6;
        const float* qp = &qs[rq * 128 + ch * CK_];
        const float* kp = &ks[rk * 128 + ch * CK_];
        float s = 0.f;
#pragma unroll
        for (int ck = 0; ck < CK_; ck++) s = fmaf(qp[ck], kp[ck], s);
        att_s[t] = s * 0.17677669529663687f;
    }
    __syncthreads();

    if (t < CH_ * U_) {
        const int ch = t / U_, rq = t % U_;
        const float* row = &att_s[(ch * U_ + rq) * U_];
        float m = row[0];
#pragma unroll
        for (int k = 1; k < U_; k++) m = fmaxf(m, row[k]);
        float e[U_]; float sum = 0.f;
#pragma unroll
        for (int k = 0; k < U_; k++) { e[k] = expf(row[k] - m); sum += e[k]; }
        const float inv = msk[rq] / sum;
#pragma unroll
        for (int k = 0; k < U_; k++) ap[(ch * U_ + rq) * U_ + k] = e[k] * inv;
    }
    __syncthreads();

    const long cb = (long)b * U_ * CHCV;
    for (int o = t; o < U_ * CHCV; o += 256) {
        const int uq = o / CHCV;
        const int r  = o % CHCV;
        const int ch = r / CV_;
        float s = 0.f;
#pragma unroll
        for (int k = 0; k < U_; k++)
            s = fmaf(ap[(ch * U_ + uq) * U_ + k], base[k * QKVN + 256 + r], s);
        __nv_bfloat16 h, l; split2(s, h, l);
        g_ctxh[cb + o] = h; g_ctxl[cb + o] = l;
    }
}

// ---------------- launch -------------------------------------------------
extern "C" void kernel_launch(void* const* d_in, const int* in_sizes, int n_in,
                              void* d_out, int out_size) {
    (void)in_sizes; (void)n_in; (void)out_size;
    const float* x    = (const float*)d_in[0];
    const float* hs   = (const float*)d_in[1];
    const float* Wk   = (const float*)d_in[2];
    const float* bk   = (const float*)d_in[3];
    const float* Wv   = (const float*)d_in[4];
    const float* bv   = (const float*)d_in[5];
    const float* Wq   = (const float*)d_in[6];
    const float* Wq_p = (const float*)d_in[7];
    const float* Wk_p = (const float*)d_in[8];
    const float* Wv_p = (const float*)d_in[9];
    const float* Wo   = (const float*)d_in[10];
    const float* sw   = (const float*)d_in[11];
    const float* gwx  = (const float*)d_in[12];
    const float* gwh  = (const float*)d_in[13];
    float* out = (float*)d_out;

    // allow 66KB dynamic smem on the tensor GEMMs (idempotent host calls)
    cudaFuncSetAttribute(tg_gx,  cudaFuncAttributeMaxDynamicSharedMemorySize, SMEM_DYN);
    cudaFuncSetAttribute(tg_gh,  cudaFuncAttributeMaxDynamicSharedMemorySize, SMEM_DYN);
    cudaFuncSetAttribute(tg_qkv, cudaFuncAttributeMaxDynamicSharedMemorySize, SMEM_DYN);
    cudaFuncSetAttribute(tg_out, cudaFuncAttributeMaxDynamicSharedMemorySize, SMEM_DYN);

    // stage 1: projections + scores (+ independent preprocessing)
    gemm_xk<<<dim3(1, 32, 1), 256>>>(x, Wk, bk);
    gemm_xv<<<dim3(4, 32, 1), 256>>>(x, Wv, bv);   // fused v0 hi/lo split
    gemm_ql<<<dim3(1, 32, U_), 256>>>(hs, Wq);
    score_kernel<<<B_, 192>>>(bk);
    split_hs<<<(B_ * UH_) / 256, 256>>>(hs);
    split_wo<<<(U_ * CHCV * CV_) / 256, 256>>>(Wo);
    pack_kernel<<<(U_ * H_ * QKVN) / 256, 256>>>(Wq_p, Wk_p, Wv_p);
    blend_kernel<<<(U_ * IV_ * H3_) / 256, 256>>>(gwx, sw, 0);
    blend_kernel<<<(U_ * H_ * H3_) / 256, 256>>>(gwh, sw, 1);
    bvwx_kernel<<<(U_ * H3_ + 255) / 256, 256>>>(bv);

    // stage 2: GRU gates (tensor) + hidden update
    tg_gx<<<dim3(H3_ / 128, 32, U_), 256, SMEM_DYN>>>();
    tg_gh<<<dim3(H3_ / 128, 32, U_), 256, SMEM_DYN>>>();
    gru_kernel<<<(B_ * U_ * H_) / 256, 256>>>(hs);

    // stage 3: qkv (tensor) + attention + output projection (tensor, fused blend)
    tg_qkv<<<dim3(QKVN / 128, 32, U_), 256, SMEM_DYN>>>();
    attn_kernel<<<B_, 256>>>();
    tg_out<<<dim3(H_ / 128, 32, U_), 256, SMEM_DYN>>>(hs, out);
}